// round 13
// baseline (speedup 1.0000x reference)
#include <cuda_runtime.h>
#include <cuda_bf16.h>

// Dead-code-eliminated Net2 BSDE recurrence.
// ARITHMETIC IS BIT-FROZEN to the passing trajectory (rel_err 1.627573e-05).
// Serial loop: verbatim Round-5 champion (branchless 3-arm select + bit-exact
// two-FMA div3). Its 44 cyc/iter chain (7 frozen roundings in mid + selects +
// update) is the irreducible floor: predication can't skip the mid depth
// (FSEL waits on both inputs) and real branches regressed (R9, BSSY/BSYNC).
//
// Round-13 changes (phase-1 gate only, bit-neutral):
//  - sqrtf(dt) hoisted OFF the producer's post-tree path: s_sq[k] =
//    sqrtf(tlist[k]) precomputed by threads 40-79 during the L2-latency
//    window. Same sqrt.rn sequence -> same bits; term3 = s * s_sq[k] rounds
//    the identical product. Saves ~40 cyc on the gate.
//  - gu_s production moved to single-step warps 16-19 (threads 512-611),
//    off-loading the gating dual-step warps. Same expression -> same bits.

#define D_DIM    100
#define N_STEPS  40
#define NWARPS   32
#define NTHREADS (NWARPS * 32)   // 1024
#define GU_BASE  512             // threads 512..611 compute gu_s

__device__ __forceinline__ float div3(float x) {
    // Correctly-rounded x/3 (== FDIV bits): Brisebarre-Muller two-FMA scheme.
    const float C_HI = 0.33333334f;       // RN(1/3)
    const float C_LO = -9.9341075e-09f;   // RN(1/3 - C_HI) = -1/(3*2^25)
    return __fmaf_rn(x, C_HI, x * C_LO);
}

__global__ void net2_u_kernel(const float* __restrict__ x0,
                              const float* __restrict__ tlist,
                              const float* __restrict__ noise,   // (N_STEPS, D, 1)
                              const float* __restrict__ u0,
                              const float* __restrict__ gu0,     // (D, 1)
                              float* __restrict__ out) {
    __shared__ float term3[N_STEPS];
    __shared__ float s_dt[N_STEPS];
    __shared__ float s_sq[N_STEPS];
    __shared__ float gu_s[D_DIM];

    const int tid  = threadIdx.x;
    const int warp = tid >> 5;
    const int lane = tid & 31;

    // ---- Issue all global loads up front ----
    float ustart = 0.0f;
    if (tid == 0) ustart = u0[0];
    if (tid < N_STEPS) s_dt[tid] = tlist[tid];
    // sqrt hoist: computed during the load-latency window, off the gate.
    if (tid >= N_STEPS && tid < 2 * N_STEPS) s_sq[tid - N_STEPS] = sqrtf(tlist[tid - N_STEPS]);

    // Preload this warp's noise elements (frozen lane mapping: lane, +32,
    // +64, +96; element lane+96 exists only for lane < 4).
    const bool tail = (lane < (D_DIM - 96));   // lane < 4
    float a0, a1, a2, a3 = 0.0f;
    float b0 = 0.0f, b1 = 0.0f, b2 = 0.0f, b3 = 0.0f;
    int k0, k1 = -1;
    if (warp < 8) { k0 = warp; k1 = warp + 32; } else { k0 = warp; }
    {
        const float* n0 = noise + k0 * D_DIM;
        a0 = n0[lane]; a1 = n0[lane + 32]; a2 = n0[lane + 64];
        if (tail) a3 = n0[lane + 96];
        if (k1 >= 0) {
            const float* n1 = noise + k1 * D_DIM;
            b0 = n1[lane]; b1 = n1[lane + 32]; b2 = n1[lane + 64];
            if (tail) b3 = n1[lane + 96];
        }
    }

    // gu computed once (bit-identical expression) by lightly-loaded
    // single-step warps 16-19.
    if (tid >= GU_BASE && tid < GU_BASE + D_DIM) {
        int i = tid - GU_BASE;
        gu_s[i] = 0.2f * x0[i] * gu0[i];
    }

    __syncthreads();

    // ---- Frozen dot products from smem gu + register noise ----
    {
        float g0 = gu_s[lane], g1 = gu_s[lane + 32], g2 = gu_s[lane + 64];
        float g3 = tail ? gu_s[lane + 96] : 0.0f;

        if (k1 >= 0) {
            float s0 = 0.0f, s1 = 0.0f;
            s0 += g0 * a0;  s1 += g0 * b0;
            s0 += g1 * a1;  s1 += g1 * b1;
            s0 += g2 * a2;  s1 += g2 * b2;
            if (tail) { s0 += g3 * a3; s1 += g3 * b3; }
            #pragma unroll
            for (int off = 16; off > 0; off >>= 1) {
                s0 += __shfl_down_sync(0xFFFFFFFFu, s0, off);
                s1 += __shfl_down_sync(0xFFFFFFFFu, s1, off);
            }
            if (lane == 0) {
                term3[k0] = s0 * s_sq[k0];
                term3[k1] = s1 * s_sq[k1];
            }
        } else {
            float s = 0.0f;
            s += g0 * a0;
            s += g1 * a1;
            s += g2 * a2;
            if (tail) s += g3 * a3;
            #pragma unroll
            for (int off = 16; off > 0; off >>= 1)
                s += __shfl_down_sync(0xFFFFFFFFu, s, off);
            if (lane == 0)
                term3[k0] = s * s_sq[k0];
        }
    }

    __syncthreads();

    // ---- Verbatim Round-5 serial loop (frozen) ----
    if (tid == 0) {
        float u = ustart;
        #pragma unroll
        for (int k = 0; k < N_STEPS; k++) {
            float dt = s_dt[k];
            float low  = div3(-0.02f * u) - 0.02f * u;
            float high = div3(-0.002f * u) - 0.02f * u;
            float mid  = div3(-(70.0f - 50.0f) / (0.02f - 0.2f) * (u - 50.0f)) * u
                         - (0.2f / 3.0f) * u - 0.02f * u;
            float f = (u < 50.0f) ? low : ((u >= 70.0f) ? high : mid);
            u = u - f * dt + term3[k];
        }
        out[0] = u;
    }
}

extern "C" void kernel_launch(void* const* d_in, const int* in_sizes, int n_in,
                              void* d_out, int out_size) {
    const float* x0    = (const float*)d_in[0];
    const float* tlist = (const float*)d_in[1];
    const float* noise = (const float*)d_in[2];
    const float* u0    = (const float*)d_in[3];
    const float* gu0   = (const float*)d_in[4];
    float* out = (float*)d_out;

    net2_u_kernel<<<1, NTHREADS>>>(x0, tlist, noise, u0, gu0, out);
}

// round 14
// speedup vs baseline: 1.1192x; 1.1192x over previous
#include <cuda_runtime.h>
#include <cuda_bf16.h>

// Dead-code-eliminated Net2 BSDE recurrence.
// ARITHMETIC IS BIT-FROZEN to the passing trajectory (rel_err 1.627573e-05).
// Serial loop: verbatim Round-5 champion (branchless 3-arm select + bit-exact
// two-FMA div3); its ~44 cyc/iter chain is the frozen-rounding floor.
// Phase 1: Round-12 champion structure (gu_s computed once by threads 0-99,
// noise preloaded to registers, smem-fed dots).
//
// Round-13 lesson: the sqrt hoist landed on threads 40-79 = WARPS 1-2, the
// dual-step GATING warps -> extended the barrier gate, regressed 1.4us.
// Round-14: revert to R12 exactly, re-apply the sqrt hoist on threads
// 704-743 (warps 22-23, single-step warps with slack): s_sq[k] =
// sqrtf(tlist[k]) computed off the gating path; producers then do
// term3 = s * s_sq[k] (LDS+FMUL) instead of LDS+sqrt.rn+FMUL after the tree.
// Same sqrt instruction on same bits -> same bits everywhere.

#define D_DIM    100
#define N_STEPS  40
#define NWARPS   32
#define NTHREADS (NWARPS * 32)   // 1024
#define SQ_BASE  704             // threads 704..743 (warps 22-23) compute s_sq

__device__ __forceinline__ float div3(float x) {
    // Correctly-rounded x/3 (== FDIV bits): Brisebarre-Muller two-FMA scheme.
    const float C_HI = 0.33333334f;       // RN(1/3)
    const float C_LO = -9.9341075e-09f;   // RN(1/3 - C_HI) = -1/(3*2^25)
    return __fmaf_rn(x, C_HI, x * C_LO);
}

__global__ void net2_u_kernel(const float* __restrict__ x0,
                              const float* __restrict__ tlist,
                              const float* __restrict__ noise,   // (N_STEPS, D, 1)
                              const float* __restrict__ u0,
                              const float* __restrict__ gu0,     // (D, 1)
                              float* __restrict__ out) {
    __shared__ float term3[N_STEPS];
    __shared__ float s_dt[N_STEPS];
    __shared__ float s_sq[N_STEPS];
    __shared__ float gu_s[D_DIM];

    const int tid  = threadIdx.x;
    const int warp = tid >> 5;
    const int lane = tid & 31;

    // ---- Issue all global loads up front ----
    float ustart = 0.0f;
    if (tid == 0) ustart = u0[0];
    if (tid < N_STEPS) s_dt[tid] = tlist[tid];
    // sqrt hoist on single-step warps 22-23 (slack warps, off the gate).
    if (tid >= SQ_BASE && tid < SQ_BASE + N_STEPS)
        s_sq[tid - SQ_BASE] = sqrtf(tlist[tid - SQ_BASE]);

    // Preload this warp's noise elements (frozen lane mapping: lane, +32,
    // +64, +96; element lane+96 exists only for lane < 4).
    const bool tail = (lane < (D_DIM - 96));   // lane < 4
    float a0, a1, a2, a3 = 0.0f;
    float b0 = 0.0f, b1 = 0.0f, b2 = 0.0f, b3 = 0.0f;
    int k0, k1 = -1;
    if (warp < 8) { k0 = warp; k1 = warp + 32; } else { k0 = warp; }
    {
        const float* n0 = noise + k0 * D_DIM;
        a0 = n0[lane]; a1 = n0[lane + 32]; a2 = n0[lane + 64];
        if (tail) a3 = n0[lane + 96];
        if (k1 >= 0) {
            const float* n1 = noise + k1 * D_DIM;
            b0 = n1[lane]; b1 = n1[lane + 32]; b2 = n1[lane + 64];
            if (tail) b3 = n1[lane + 96];
        }
    }

    // gu computed once (bit-identical expression) -- R12 placement.
    if (tid < D_DIM) gu_s[tid] = 0.2f * x0[tid] * gu0[tid];

    __syncthreads();

    // ---- Frozen dot products from smem gu + register noise ----
    {
        float g0 = gu_s[lane], g1 = gu_s[lane + 32], g2 = gu_s[lane + 64];
        float g3 = tail ? gu_s[lane + 96] : 0.0f;

        if (k1 >= 0) {
            float s0 = 0.0f, s1 = 0.0f;
            s0 += g0 * a0;  s1 += g0 * b0;
            s0 += g1 * a1;  s1 += g1 * b1;
            s0 += g2 * a2;  s1 += g2 * b2;
            if (tail) { s0 += g3 * a3; s1 += g3 * b3; }
            #pragma unroll
            for (int off = 16; off > 0; off >>= 1) {
                s0 += __shfl_down_sync(0xFFFFFFFFu, s0, off);
                s1 += __shfl_down_sync(0xFFFFFFFFu, s1, off);
            }
            if (lane == 0) {
                term3[k0] = s0 * s_sq[k0];
                term3[k1] = s1 * s_sq[k1];
            }
        } else {
            float s = 0.0f;
            s += g0 * a0;
            s += g1 * a1;
            s += g2 * a2;
            if (tail) s += g3 * a3;
            #pragma unroll
            for (int off = 16; off > 0; off >>= 1)
                s += __shfl_down_sync(0xFFFFFFFFu, s, off);
            if (lane == 0)
                term3[k0] = s * s_sq[k0];
        }
    }

    __syncthreads();

    // ---- Verbatim Round-5 serial loop (frozen) ----
    if (tid == 0) {
        float u = ustart;
        #pragma unroll
        for (int k = 0; k < N_STEPS; k++) {
            float dt = s_dt[k];
            float low  = div3(-0.02f * u) - 0.02f * u;
            float high = div3(-0.002f * u) - 0.02f * u;
            float mid  = div3(-(70.0f - 50.0f) / (0.02f - 0.2f) * (u - 50.0f)) * u
                         - (0.2f / 3.0f) * u - 0.02f * u;
            float f = (u < 50.0f) ? low : ((u >= 70.0f) ? high : mid);
            u = u - f * dt + term3[k];
        }
        out[0] = u;
    }
}

extern "C" void kernel_launch(void* const* d_in, const int* in_sizes, int n_in,
                              void* d_out, int out_size) {
    const float* x0    = (const float*)d_in[0];
    const float* tlist = (const float*)d_in[1];
    const float* noise = (const float*)d_in[2];
    const float* u0    = (const float*)d_in[3];
    const float* gu0   = (const float*)d_in[4];
    float* out = (float*)d_out;

    net2_u_kernel<<<1, NTHREADS>>>(x0, tlist, noise, u0, gu0, out);
}